// round 7
// baseline (speedup 1.0000x reference)
#include <cuda_runtime.h>
#include <math.h>
#include <stdint.h>

#define V 32000
#define H 1024
#define T 32
#define B 64
#define SOS_INDEX 1
#define EOS_INDEX 2
#define GATES (4*H)

// Persistent decode state (no allocations allowed)
__device__ float g_x[B*H];       // current input embedding
__device__ float g_h[B*H];       // hidden state
__device__ float g_c[B*H];       // cell state
__device__ float g_gates[B*GATES];

// ---------------------------------------------------------------------------
__global__ void init_kernel(const float* __restrict__ E,
                            const float* __restrict__ eh,
                            const float* __restrict__ ec) {
    int i = blockIdx.x * blockDim.x + threadIdx.x;   // 0 .. B*H
    int k = i & (H - 1);
    g_x[i] = E[SOS_INDEX * H + k];
    g_h[i] = eh[i];
    g_c[i] = ec[i];
}

// ---------------------------------------------------------------------------
// TF32 helpers (3xTF32 fp32 emulation)
// ---------------------------------------------------------------------------
__device__ __forceinline__ uint32_t f2tf32(float x) {
    uint32_t r;
    asm("cvt.rna.tf32.f32 %0, %1;" : "=r"(r) : "f"(x));
    return r;
}
__device__ __forceinline__ void split_tf32(float x, float& hi, float& lo) {
    hi = __uint_as_float(f2tf32(x));
    lo = __uint_as_float(f2tf32(x - hi));
}
__device__ __forceinline__ void mma_tf32(float c[4], float4 a, float2 b) {
    asm volatile(
        "mma.sync.aligned.m16n8k8.row.col.f32.tf32.tf32.f32 "
        "{%0,%1,%2,%3}, {%4,%5,%6,%7}, {%8,%9}, {%0,%1,%2,%3};"
        : "+f"(c[0]), "+f"(c[1]), "+f"(c[2]), "+f"(c[3])
        : "r"(__float_as_uint(a.x)), "r"(__float_as_uint(a.y)),
          "r"(__float_as_uint(a.z)), "r"(__float_as_uint(a.w)),
          "r"(__float_as_uint(b.x)), "r"(__float_as_uint(b.y)));
}

// ---------------------------------------------------------------------------
// Tensor-core GEMM: C[64 x N] = A[64 x KTOT] * W[N x KTOT]^T + bias
// hi/lo tf32 split done once at the load stage into element-major SMEM tiles
// (merged STS.128). Inner loop: LDS + HMMA with THREE independent accumulator
// chains (one per 3xTF32 pass) so no pass stalls on another pass's RAW.
// ---------------------------------------------------------------------------
#define BK 32
#define SKEW 4

template<int KTOT, int BN, bool CONCAT>
__global__ __launch_bounds__(256, 2)
void mma_gemm(const float* __restrict__ Wa, const float* __restrict__ Wb,
              const float* __restrict__ bias1, const float* __restrict__ bias2,
              float* __restrict__ out, int ldc) {
    constexpr int NF = BN / 16;           // 8-wide n fragments per warp
    constexpr int BR = BN / 32;           // B loader row chunks
    __shared__ __align__(16) float AsH[64][BK + SKEW];
    __shared__ __align__(16) float AsL[64][BK + SKEW];
    __shared__ __align__(16) float BsH[BN][BK + SKEW];
    __shared__ __align__(16) float BsL[BN][BK + SKEW];

    const int n0blk = blockIdx.x * BN;
    const int tid   = threadIdx.x;
    const int warp  = tid >> 5;
    const int lane  = tid & 31;
    const int gid   = lane >> 2;
    const int tig   = lane & 3;

    const int m0  = (warp >> 1) * 16;      // warp M offset (0,16,32,48)
    const int n0w = (warp & 1) * (BN / 2); // warp N offset

    const int lm  = tid >> 3;              // loader row 0..31
    const int lk4 = (tid & 7) * 4;         // loader k offset (float4)

    float4 aR[2];
    float4 bR[BR];

    auto gload = [&](int k0) {
        const int kg = k0 + lk4;
        #pragma unroll
        for (int r = 0; r < 2; r++) {
            int m = lm + r * 32;
            const float* src = CONCAT
                ? ((kg < H) ? (g_x + m * H + kg) : (g_h + m * H + (kg - H)))
                : (g_h + m * H + kg);
            aR[r] = *reinterpret_cast<const float4*>(src);
        }
        #pragma unroll
        for (int r = 0; r < BR; r++) {
            int n = lm + r * 32;
            const float* src = CONCAT
                ? ((kg < H) ? (Wa + (size_t)(n0blk + n) * H + kg)
                            : (Wb + (size_t)(n0blk + n) * H + (kg - H)))
                : (Wa + (size_t)(n0blk + n) * KTOT + kg);
            bR[r] = *reinterpret_cast<const float4*>(src);
        }
    };

    auto store_split = [&]() {
        #pragma unroll
        for (int r = 0; r < 2; r++) {
            int m = lm + r * 32;
            float v[4] = {aR[r].x, aR[r].y, aR[r].z, aR[r].w};
            float h[4], l[4];
            #pragma unroll
            for (int j = 0; j < 4; j++) split_tf32(v[j], h[j], l[j]);
            *reinterpret_cast<float4*>(&AsH[m][lk4]) = make_float4(h[0], h[1], h[2], h[3]);
            *reinterpret_cast<float4*>(&AsL[m][lk4]) = make_float4(l[0], l[1], l[2], l[3]);
        }
        #pragma unroll
        for (int r = 0; r < BR; r++) {
            int n = lm + r * 32;
            float v[4] = {bR[r].x, bR[r].y, bR[r].z, bR[r].w};
            float h[4], l[4];
            #pragma unroll
            for (int j = 0; j < 4; j++) split_tf32(v[j], h[j], l[j]);
            *reinterpret_cast<float4*>(&BsH[n][lk4]) = make_float4(h[0], h[1], h[2], h[3]);
            *reinterpret_cast<float4*>(&BsL[n][lk4]) = make_float4(l[0], l[1], l[2], l[3]);
        }
    };

    // Three independent accumulator chains (one per 3xTF32 pass).
    float chh[NF][4], clh[NF][4], chl[NF][4];
    #pragma unroll
    for (int nf = 0; nf < NF; nf++)
        #pragma unroll
        for (int j = 0; j < 4; j++) { chh[nf][j] = 0.f; clh[nf][j] = 0.f; chl[nf][j] = 0.f; }

    gload(0);
    for (int k0 = 0; k0 < KTOT; k0 += BK) {
        store_split();
        __syncthreads();
        if (k0 + BK < KTOT) gload(k0 + BK);    // prefetch next tile into regs

        #pragma unroll
        for (int ks = 0; ks < BK / 8; ks++) {
            const int kk = ks * 8;
            const int ra = m0 + gid, rb = m0 + gid + 8;
            float4 ah = make_float4(AsH[ra][kk + tig], AsH[rb][kk + tig],
                                    AsH[ra][kk + tig + 4], AsH[rb][kk + tig + 4]);
            float4 al = make_float4(AsL[ra][kk + tig], AsL[rb][kk + tig],
                                    AsL[ra][kk + tig + 4], AsL[rb][kk + tig + 4]);
            float2 bh[NF], bl[NF];
            #pragma unroll
            for (int nf = 0; nf < NF; nf++) {
                int n = n0w + nf * 8 + gid;
                bh[nf] = make_float2(BsH[n][kk + tig], BsH[n][kk + tig + 4]);
                bl[nf] = make_float2(BsL[n][kk + tig], BsL[n][kk + tig + 4]);
            }
            // One MMA per chain per ks: reuse distance = 3*NF HMMAs.
            #pragma unroll
            for (int nf = 0; nf < NF; nf++) mma_tf32(clh[nf], al, bh[nf]);
            #pragma unroll
            for (int nf = 0; nf < NF; nf++) mma_tf32(chl[nf], ah, bl[nf]);
            #pragma unroll
            for (int nf = 0; nf < NF; nf++) mma_tf32(chh[nf], ah, bh[nf]);
        }
        __syncthreads();
    }

    // ---- epilogue: combine chains + bias + store ----
    const int mr0 = m0 + gid;
    const int mr1 = m0 + gid + 8;
    #pragma unroll
    for (int nf = 0; nf < NF; nf++) {
        int nn = n0blk + n0w + nf * 8 + tig * 2;
        float b0 = bias1[nn]     + (CONCAT ? bias2[nn]     : 0.f);
        float b1 = bias1[nn + 1] + (CONCAT ? bias2[nn + 1] : 0.f);
        float s0 = clh[nf][0] + chl[nf][0] + chh[nf][0];
        float s1 = clh[nf][1] + chl[nf][1] + chh[nf][1];
        float s2 = clh[nf][2] + chl[nf][2] + chh[nf][2];
        float s3 = clh[nf][3] + chl[nf][3] + chh[nf][3];
        *reinterpret_cast<float2*>(out + (size_t)mr0 * ldc + nn) =
            make_float2(s0 + b0, s1 + b1);
        *reinterpret_cast<float2*>(out + (size_t)mr1 * ldc + nn) =
            make_float2(s2 + b0, s3 + b1);
    }
}

// ---------------------------------------------------------------------------
// LSTM cell elementwise (PyTorch gate order i,f,g,o)
// ---------------------------------------------------------------------------
__global__ void cell_kernel() {
    int i = blockIdx.x * blockDim.x + threadIdx.x;   // B*H
    int b = i >> 10;
    int j = i & (H - 1);
    const float* g = g_gates + b * GATES;
    float ig = g[j], fg = g[j + H], gg = g[j + 2 * H], og = g[j + 3 * H];
    float c  = g_c[i];
    float si = 1.f / (1.f + expf(-ig));
    float sf = 1.f / (1.f + expf(-fg));
    float so = 1.f / (1.f + expf(-og));
    float cn = sf * c + si * tanhf(gg);
    float hn = so * tanhf(cn);
    g_c[i] = cn;
    g_h[i] = hn;
}

// ---------------------------------------------------------------------------
// Per-batch-row: argmax (first-index tiebreak), softmax EOS prob,
// greedy feedback gather x_next = E[argmax]. 1024 threads, float4 loads.
// ---------------------------------------------------------------------------
__global__ __launch_bounds__(1024)
void softmax_argmax(const float* __restrict__ logits, const float* __restrict__ E,
                    float* __restrict__ mask_out) {
    const int b    = blockIdx.x;
    const int tid  = threadIdx.x;
    const int lane = tid & 31;
    const int wrp  = tid >> 5;
    const float* row = logits + (size_t)b * V;

    // ---- pass 1: max + argmax (lowest index on ties) ----
    float best = -INFINITY; int besti = 0x7fffffff;
    for (int v = tid * 4; v < V; v += 4096) {
        float4 x = *reinterpret_cast<const float4*>(row + v);
        if (x.x > best) { best = x.x; besti = v; }
        if (x.y > best) { best = x.y; besti = v + 1; }
        if (x.z > best) { best = x.z; besti = v + 2; }
        if (x.w > best) { best = x.w; besti = v + 3; }
    }
    #pragma unroll
    for (int s = 16; s > 0; s >>= 1) {
        float ov = __shfl_down_sync(0xffffffffu, best, s);
        int   oi = __shfl_down_sync(0xffffffffu, besti, s);
        if (ov > best || (ov == best && oi < besti)) { best = ov; besti = oi; }
    }
    __shared__ float swv[32];
    __shared__ int   swi[32];
    if (lane == 0) { swv[wrp] = best; swi[wrp] = besti; }
    __syncthreads();
    __shared__ float s_gmax;
    __shared__ int   s_amax;
    if (wrp == 0) {
        float bv = swv[lane]; int bi = swi[lane];
        #pragma unroll
        for (int s = 16; s > 0; s >>= 1) {
            float ov = __shfl_down_sync(0xffffffffu, bv, s);
            int   oi = __shfl_down_sync(0xffffffffu, bi, s);
            if (ov > bv || (ov == bv && oi < bi)) { bv = ov; bi = oi; }
        }
        if (lane == 0) { s_gmax = bv; s_amax = bi; }
    }
    __syncthreads();
    const float gmax = s_gmax;
    const int   amax = s_amax;

    // ---- pass 2: sum of exp ----
    float sum = 0.f;
    for (int v = tid * 4; v < V; v += 4096) {
        float4 x = *reinterpret_cast<const float4*>(row + v);
        sum += expf(x.x - gmax) + expf(x.y - gmax)
             + expf(x.z - gmax) + expf(x.w - gmax);
    }
    #pragma unroll
    for (int s = 16; s > 0; s >>= 1)
        sum += __shfl_down_sync(0xffffffffu, sum, s);
    __shared__ float ssum[32];
    if (lane == 0) ssum[wrp] = sum;
    __syncthreads();
    if (wrp == 0) {
        float t = ssum[lane];
        #pragma unroll
        for (int s = 16; s > 0; s >>= 1)
            t += __shfl_down_sync(0xffffffffu, t, s);
        if (lane == 0) mask_out[b] = expf(row[EOS_INDEX] - gmax) / t;
    }

    // greedy feedback: x_next = E[argmax]  (H == 1024 == blockDim)
    g_x[b * H + tid] = E[(size_t)amax * H + tid];
}

// ---------------------------------------------------------------------------
extern "C" void kernel_launch(void* const* d_in, const int* in_sizes, int n_in,
                              void* d_out, int out_size) {
    const float* E    = (const float*)d_in[0];
    const float* Wih  = (const float*)d_in[1];
    const float* Whh  = (const float*)d_in[2];
    const float* bih  = (const float*)d_in[3];
    const float* bhh  = (const float*)d_in[4];
    const float* Wout = (const float*)d_in[5];
    const float* bout = (const float*)d_in[6];
    const float* eh   = (const float*)d_in[7];
    const float* ec   = (const float*)d_in[8];

    float* out   = (float*)d_out;                       // [T][B][V] logits
    float* masks = out + (size_t)T * B * V;             // [T][B]

    // Resolve DEVICE address of g_gates (host shadow addr would silently
    // write host memory via ATS on GB300).
    void* gates_dev = nullptr;
    cudaGetSymbolAddress(&gates_dev, g_gates);
    float* gates_ptr = (float*)gates_dev;

    init_kernel<<<(B * H) / 256, 256>>>(E, eh, ec);
    for (int t = 0; t < T; t++) {
        float* lg = out + (size_t)t * B * V;
        // gates: [64 x 4096] = [x|h] * [Wih|Whh]^T, BN=32 -> 128 blocks
        mma_gemm<2 * H, 32, true><<<GATES / 32, 256>>>(
            Wih, Whh, bih, bhh, gates_ptr, GATES);
        cell_kernel<<<(B * H) / 256, 256>>>();
        // logits: [64 x 32000] = h * Wout^T, BN=64 -> 500 blocks
        mma_gemm<H, 64, false><<<V / 64, 256>>>(
            Wout, nullptr, bout, nullptr, lg, V);
        softmax_argmax<<<B, 1024>>>(lg, E, masks + t * B);
    }
}

// round 8
// speedup vs baseline: 1.7427x; 1.7427x over previous
#include <cuda_runtime.h>
#include <cuda_fp16.h>
#include <math.h>
#include <stdint.h>

#define V 32000
#define H 1024
#define T 32
#define B 64
#define SOS_INDEX 1
#define EOS_INDEX 2
#define GATES (4*H)

// Persistent decode state (no allocations allowed)
__device__ float g_x[B*H];       // current input embedding
__device__ float g_h[B*H];       // hidden state
__device__ float g_c[B*H];       // cell state
__device__ float g_gates[B*GATES];

// ---------------------------------------------------------------------------
__global__ void init_kernel(const float* __restrict__ E,
                            const float* __restrict__ eh,
                            const float* __restrict__ ec) {
    int i = blockIdx.x * blockDim.x + threadIdx.x;   // 0 .. B*H
    int k = i & (H - 1);
    g_x[i] = E[SOS_INDEX * H + k];
    g_h[i] = eh[i];
    g_c[i] = ec[i];
}

// ---------------------------------------------------------------------------
// fp16 2-term split helpers (exact-product fp32 emulation):
//   A = Ah + Al'/2048,  Ah = fp16(A),  Al' = fp16((A-Ah)*2048)
//   C = Ah*Bh + (Al'*Bh + Ah*Bl')/2048   (dropped term ~2^-22 rel)
// ---------------------------------------------------------------------------
#define RSCALE 2048.0f
#define RINV   (1.0f / 2048.0f)

__device__ __forceinline__ void split_f16(float x, __half& hi, __half& lo) {
    hi = __float2half_rn(x);
    lo = __float2half_rn((x - __half2float(hi)) * RSCALE);
}
__device__ __forceinline__ uint32_t pack2(__half a, __half b) {
    __half2 h = __halves2half2(a, b);
    return *reinterpret_cast<uint32_t*>(&h);
}
__device__ __forceinline__ void mma_f16(float c[4], const uint32_t a[4],
                                        uint32_t b0, uint32_t b1) {
    asm volatile(
        "mma.sync.aligned.m16n8k16.row.col.f32.f16.f16.f32 "
        "{%0,%1,%2,%3}, {%4,%5,%6,%7}, {%8,%9}, {%0,%1,%2,%3};"
        : "+f"(c[0]), "+f"(c[1]), "+f"(c[2]), "+f"(c[3])
        : "r"(a[0]), "r"(a[1]), "r"(a[2]), "r"(a[3]), "r"(b0), "r"(b1));
}

// ---------------------------------------------------------------------------
// Tensor-core GEMM: C[64 x N] = A[64 x KTOT] * W[N x KTOT]^T + bias
// fp16 hi / scaled-lo split done once at the load stage into element-major
// SMEM half tiles (80-byte rows: conflict-free producer STS.64 and consumer
// fragment LDS.32). Inner loop: m16n8k16 HMMA, two accumulator chains.
// ---------------------------------------------------------------------------
#define BK 32
#define SKEW_H 8   // halves; row = 40 halves = 80 bytes

template<int KTOT, int BN, bool CONCAT>
__global__ __launch_bounds__(256)
void mma_gemm(const float* __restrict__ Wa, const float* __restrict__ Wb,
              const float* __restrict__ bias1, const float* __restrict__ bias2,
              float* __restrict__ out, int ldc) {
    constexpr int NF = BN / 16;           // 8-wide n fragments per warp
    constexpr int BR = BN / 32;           // B loader row chunks
    __shared__ __align__(16) __half AsH[64][BK + SKEW_H];
    __shared__ __align__(16) __half AsL[64][BK + SKEW_H];
    __shared__ __align__(16) __half BsH[BN][BK + SKEW_H];
    __shared__ __align__(16) __half BsL[BN][BK + SKEW_H];

    const int n0blk = blockIdx.x * BN;
    const int tid   = threadIdx.x;
    const int warp  = tid >> 5;
    const int lane  = tid & 31;
    const int gid   = lane >> 2;
    const int tig   = lane & 3;

    const int m0  = (warp >> 1) * 16;      // warp M offset (0,16,32,48)
    const int n0w = (warp & 1) * (BN / 2); // warp N offset

    const int lm  = tid >> 3;              // loader row 0..31
    const int lk4 = (tid & 7) * 4;         // loader k offset (float4)

    float4 aR[2];
    float4 bR[BR];

    auto gload = [&](int k0) {
        const int kg = k0 + lk4;
        #pragma unroll
        for (int r = 0; r < 2; r++) {
            int m = lm + r * 32;
            const float* src = CONCAT
                ? ((kg < H) ? (g_x + m * H + kg) : (g_h + m * H + (kg - H)))
                : (g_h + m * H + kg);
            aR[r] = *reinterpret_cast<const float4*>(src);
        }
        #pragma unroll
        for (int r = 0; r < BR; r++) {
            int n = lm + r * 32;
            const float* src = CONCAT
                ? ((kg < H) ? (Wa + (size_t)(n0blk + n) * H + kg)
                            : (Wb + (size_t)(n0blk + n) * H + (kg - H)))
                : (Wa + (size_t)(n0blk + n) * KTOT + kg);
            bR[r] = *reinterpret_cast<const float4*>(src);
        }
    };

    auto store_split = [&]() {
        #pragma unroll
        for (int r = 0; r < 2; r++) {
            int m = lm + r * 32;
            float v[4] = {aR[r].x, aR[r].y, aR[r].z, aR[r].w};
            __half h[4], l[4];
            #pragma unroll
            for (int j = 0; j < 4; j++) split_f16(v[j], h[j], l[j]);
            uint2 ph = make_uint2(pack2(h[0], h[1]), pack2(h[2], h[3]));
            uint2 pl = make_uint2(pack2(l[0], l[1]), pack2(l[2], l[3]));
            *reinterpret_cast<uint2*>(&AsH[m][lk4]) = ph;
            *reinterpret_cast<uint2*>(&AsL[m][lk4]) = pl;
        }
        #pragma unroll
        for (int r = 0; r < BR; r++) {
            int n = lm + r * 32;
            float v[4] = {bR[r].x, bR[r].y, bR[r].z, bR[r].w};
            __half h[4], l[4];
            #pragma unroll
            for (int j = 0; j < 4; j++) split_f16(v[j], h[j], l[j]);
            uint2 ph = make_uint2(pack2(h[0], h[1]), pack2(h[2], h[3]));
            uint2 pl = make_uint2(pack2(l[0], l[1]), pack2(l[2], l[3]));
            *reinterpret_cast<uint2*>(&BsH[n][lk4]) = ph;
            *reinterpret_cast<uint2*>(&BsL[n][lk4]) = pl;
        }
    };

    // Two accumulator chains: c1 = Ah*Bh (scale 1), c2 = Al'*Bh + Ah*Bl'
    float c1[NF][4], c2[NF][4];
    #pragma unroll
    for (int nf = 0; nf < NF; nf++)
        #pragma unroll
        for (int j = 0; j < 4; j++) { c1[nf][j] = 0.f; c2[nf][j] = 0.f; }

    gload(0);
    for (int k0 = 0; k0 < KTOT; k0 += BK) {
        store_split();
        __syncthreads();
        if (k0 + BK < KTOT) gload(k0 + BK);    // prefetch next tile into regs

        #pragma unroll
        for (int ks = 0; ks < BK / 16; ks++) {
            const int kb = ks * 16;
            const int ra = m0 + gid, rb = m0 + gid + 8;
            uint32_t ah[4], al[4];
            ah[0] = *reinterpret_cast<const uint32_t*>(&AsH[ra][kb + 2 * tig]);
            ah[1] = *reinterpret_cast<const uint32_t*>(&AsH[rb][kb + 2 * tig]);
            ah[2] = *reinterpret_cast<const uint32_t*>(&AsH[ra][kb + 8 + 2 * tig]);
            ah[3] = *reinterpret_cast<const uint32_t*>(&AsH[rb][kb + 8 + 2 * tig]);
            al[0] = *reinterpret_cast<const uint32_t*>(&AsL[ra][kb + 2 * tig]);
            al[1] = *reinterpret_cast<const uint32_t*>(&AsL[rb][kb + 2 * tig]);
            al[2] = *reinterpret_cast<const uint32_t*>(&AsL[ra][kb + 8 + 2 * tig]);
            al[3] = *reinterpret_cast<const uint32_t*>(&AsL[rb][kb + 8 + 2 * tig]);

            uint32_t bh[NF][2];
            #pragma unroll
            for (int nf = 0; nf < NF; nf++) {
                int n = n0w + nf * 8 + gid;
                bh[nf][0] = *reinterpret_cast<const uint32_t*>(&BsH[n][kb + 2 * tig]);
                bh[nf][1] = *reinterpret_cast<const uint32_t*>(&BsH[n][kb + 8 + 2 * tig]);
            }
            // pass 1: c2 += Al'*Bh
            #pragma unroll
            for (int nf = 0; nf < NF; nf++) mma_f16(c2[nf], al, bh[nf][0], bh[nf][1]);
            // pass 2: c1 += Ah*Bh
            #pragma unroll
            for (int nf = 0; nf < NF; nf++) mma_f16(c1[nf], ah, bh[nf][0], bh[nf][1]);
            // pass 3: c2 += Ah*Bl'
            #pragma unroll
            for (int nf = 0; nf < NF; nf++) {
                int n = n0w + nf * 8 + gid;
                uint32_t bl0 = *reinterpret_cast<const uint32_t*>(&BsL[n][kb + 2 * tig]);
                uint32_t bl1 = *reinterpret_cast<const uint32_t*>(&BsL[n][kb + 8 + 2 * tig]);
                mma_f16(c2[nf], ah, bl0, bl1);
            }
        }
        __syncthreads();
    }

    // ---- epilogue: combine chains + bias + store ----
    const int mr0 = m0 + gid;
    const int mr1 = m0 + gid + 8;
    #pragma unroll
    for (int nf = 0; nf < NF; nf++) {
        int nn = n0blk + n0w + nf * 8 + tig * 2;
        float b0 = bias1[nn]     + (CONCAT ? bias2[nn]     : 0.f);
        float b1 = bias1[nn + 1] + (CONCAT ? bias2[nn + 1] : 0.f);
        float s0 = c1[nf][0] + c2[nf][0] * RINV;
        float s1 = c1[nf][1] + c2[nf][1] * RINV;
        float s2 = c1[nf][2] + c2[nf][2] * RINV;
        float s3 = c1[nf][3] + c2[nf][3] * RINV;
        *reinterpret_cast<float2*>(out + (size_t)mr0 * ldc + nn) =
            make_float2(s0 + b0, s1 + b1);
        *reinterpret_cast<float2*>(out + (size_t)mr1 * ldc + nn) =
            make_float2(s2 + b0, s3 + b1);
    }
}

// ---------------------------------------------------------------------------
// LSTM cell elementwise (PyTorch gate order i,f,g,o)
// ---------------------------------------------------------------------------
__global__ void cell_kernel() {
    int i = blockIdx.x * blockDim.x + threadIdx.x;   // B*H
    int b = i >> 10;
    int j = i & (H - 1);
    const float* g = g_gates + b * GATES;
    float ig = g[j], fg = g[j + H], gg = g[j + 2 * H], og = g[j + 3 * H];
    float c  = g_c[i];
    float si = 1.f / (1.f + expf(-ig));
    float sf = 1.f / (1.f + expf(-fg));
    float so = 1.f / (1.f + expf(-og));
    float cn = sf * c + si * tanhf(gg);
    float hn = so * tanhf(cn);
    g_c[i] = cn;
    g_h[i] = hn;
}

// ---------------------------------------------------------------------------
// Per-batch-row: argmax (first-index tiebreak), softmax EOS prob,
// greedy feedback gather x_next = E[argmax]. 1024 threads, float4 loads.
// ---------------------------------------------------------------------------
__global__ __launch_bounds__(1024)
void softmax_argmax(const float* __restrict__ logits, const float* __restrict__ E,
                    float* __restrict__ mask_out) {
    const int b    = blockIdx.x;
    const int tid  = threadIdx.x;
    const int lane = tid & 31;
    const int wrp  = tid >> 5;
    const float* row = logits + (size_t)b * V;

    // ---- pass 1: max + argmax (lowest index on ties) ----
    float best = -INFINITY; int besti = 0x7fffffff;
    for (int v = tid * 4; v < V; v += 4096) {
        float4 x = *reinterpret_cast<const float4*>(row + v);
        if (x.x > best) { best = x.x; besti = v; }
        if (x.y > best) { best = x.y; besti = v + 1; }
        if (x.z > best) { best = x.z; besti = v + 2; }
        if (x.w > best) { best = x.w; besti = v + 3; }
    }
    #pragma unroll
    for (int s = 16; s > 0; s >>= 1) {
        float ov = __shfl_down_sync(0xffffffffu, best, s);
        int   oi = __shfl_down_sync(0xffffffffu, besti, s);
        if (ov > best || (ov == best && oi < besti)) { best = ov; besti = oi; }
    }
    __shared__ float swv[32];
    __shared__ int   swi[32];
    if (lane == 0) { swv[wrp] = best; swi[wrp] = besti; }
    __syncthreads();
    __shared__ float s_gmax;
    __shared__ int   s_amax;
    if (wrp == 0) {
        float bv = swv[lane]; int bi = swi[lane];
        #pragma unroll
        for (int s = 16; s > 0; s >>= 1) {
            float ov = __shfl_down_sync(0xffffffffu, bv, s);
            int   oi = __shfl_down_sync(0xffffffffu, bi, s);
            if (ov > bv || (ov == bv && oi < bi)) { bv = ov; bi = oi; }
        }
        if (lane == 0) { s_gmax = bv; s_amax = bi; }
    }
    __syncthreads();
    const float gmax = s_gmax;
    const int   amax = s_amax;

    // ---- pass 2: sum of exp ----
    float sum = 0.f;
    for (int v = tid * 4; v < V; v += 4096) {
        float4 x = *reinterpret_cast<const float4*>(row + v);
        sum += expf(x.x - gmax) + expf(x.y - gmax)
             + expf(x.z - gmax) + expf(x.w - gmax);
    }
    #pragma unroll
    for (int s = 16; s > 0; s >>= 1)
        sum += __shfl_down_sync(0xffffffffu, sum, s);
    __shared__ float ssum[32];
    if (lane == 0) ssum[wrp] = sum;
    __syncthreads();
    if (wrp == 0) {
        float t = ssum[lane];
        #pragma unroll
        for (int s = 16; s > 0; s >>= 1)
            t += __shfl_down_sync(0xffffffffu, t, s);
        if (lane == 0) mask_out[b] = expf(row[EOS_INDEX] - gmax) / t;
    }

    // greedy feedback: x_next = E[argmax]  (H == 1024 == blockDim)
    g_x[b * H + tid] = E[(size_t)amax * H + tid];
}

// ---------------------------------------------------------------------------
extern "C" void kernel_launch(void* const* d_in, const int* in_sizes, int n_in,
                              void* d_out, int out_size) {
    const float* E    = (const float*)d_in[0];
    const float* Wih  = (const float*)d_in[1];
    const float* Whh  = (const float*)d_in[2];
    const float* bih  = (const float*)d_in[3];
    const float* bhh  = (const float*)d_in[4];
    const float* Wout = (const float*)d_in[5];
    const float* bout = (const float*)d_in[6];
    const float* eh   = (const float*)d_in[7];
    const float* ec   = (const float*)d_in[8];

    float* out   = (float*)d_out;                       // [T][B][V] logits
    float* masks = out + (size_t)T * B * V;             // [T][B]

    // Resolve DEVICE address of g_gates (host shadow addr would silently
    // write host memory via ATS on GB300).
    void* gates_dev = nullptr;
    cudaGetSymbolAddress(&gates_dev, g_gates);
    float* gates_ptr = (float*)gates_dev;

    init_kernel<<<(B * H) / 256, 256>>>(E, eh, ec);
    for (int t = 0; t < T; t++) {
        float* lg = out + (size_t)t * B * V;
        // gates: [64 x 4096] = [x|h] * [Wih|Whh]^T, BN=32 -> 128 blocks
        mma_gemm<2 * H, 32, true><<<GATES / 32, 256>>>(
            Wih, Whh, bih, bhh, gates_ptr, GATES);
        cell_kernel<<<(B * H) / 256, 256>>>();
        // logits: [64 x 32000] = h * Wout^T, BN=64 -> 500 blocks
        mma_gemm<H, 64, false><<<V / 64, 256>>>(
            Wout, nullptr, bout, nullptr, lg, V);
        softmax_argmax<<<B, 1024>>>(lg, E, masks + t * B);
    }
}

// round 12
// speedup vs baseline: 2.6370x; 1.5131x over previous
#include <cuda_runtime.h>
#include <cuda_fp16.h>
#include <math.h>
#include <stdint.h>

#define V 32000
#define H 1024
#define T 32
#define B 64
#define SOS_INDEX 1
#define EOS_INDEX 2
#define GATES (4*H)

#define RSCALE 2048.0f
#define RINV   (1.0f / 2048.0f)

// ---------------------------------------------------------------------------
// Persistent state. EVERY global that receives accesses wider than 4 bytes
// is vector-typed and accessed by vector-unit indexing (base + 16*idx),
// making misalignment structurally impossible.
// ---------------------------------------------------------------------------
__device__ float4 g_c_raw[B*H/4];
__device__ float4 g_gates_raw[B*GATES/4];
__device__ uint4  g_xH_raw[B*H/8];
__device__ uint4  g_xL_raw[B*H/8];
__device__ uint4  g_hH_raw[B*H/8];
__device__ uint4  g_hL_raw[B*H/8];
__device__ uint4  g_WihH_raw[GATES*H/8];
__device__ uint4  g_WihL_raw[GATES*H/8];
__device__ uint4  g_WhhH_raw[GATES*H/8];
__device__ uint4  g_WhhL_raw[GATES*H/8];
__device__ uint4  g_WoutH_raw[(size_t)V*H/8];
__device__ uint4  g_WoutL_raw[(size_t)V*H/8];

// scalar-access aliases (2B / 4B accesses only through these)
#define g_c     ((float*)g_c_raw)
#define g_gates ((float*)g_gates_raw)
#define g_xH    ((__half*)g_xH_raw)
#define g_xL    ((__half*)g_xL_raw)
#define g_hH    ((__half*)g_hH_raw)
#define g_hL    ((__half*)g_hL_raw)

// ---------------------------------------------------------------------------
__device__ __forceinline__ void split_f16(float x, __half& hi, __half& lo) {
    hi = __float2half_rn(x);
    lo = __float2half_rn((x - __half2float(hi)) * RSCALE);
}
__device__ __forceinline__ uint32_t pack2(__half a, __half b) {
    __half2 h = __halves2half2(a, b);
    return *reinterpret_cast<uint32_t*>(&h);
}
__device__ __forceinline__ void mma_f16(float c[4], const uint32_t a[4],
                                        uint32_t b0, uint32_t b1) {
    asm volatile(
        "mma.sync.aligned.m16n8k16.row.col.f32.f16.f16.f32 "
        "{%0,%1,%2,%3}, {%4,%5,%6,%7}, {%8,%9}, {%0,%1,%2,%3};"
        : "+f"(c[0]), "+f"(c[1]), "+f"(c[2]), "+f"(c[3])
        : "r"(a[0]), "r"(a[1]), "r"(a[2]), "r"(a[3]), "r"(b0), "r"(b1));
}

// ---------------------------------------------------------------------------
// Weight pre-split: one float4 (4 fp32) -> one uint2 of hi halves + one of lo.
// All accesses are vector-unit indexed on vector-typed pointers.
// ---------------------------------------------------------------------------
__global__ __launch_bounds__(256)
void split_weights(const float4* __restrict__ W, uint2* __restrict__ WH,
                   uint2* __restrict__ WL) {
    size_t j = (size_t)blockIdx.x * 256 + threadIdx.x;   // float4 index
    float4 v = W[j];
    __half h0, l0, h1, l1, h2, l2, h3, l3;
    split_f16(v.x, h0, l0); split_f16(v.y, h1, l1);
    split_f16(v.z, h2, l2); split_f16(v.w, h3, l3);
    WH[j] = make_uint2(pack2(h0, h1), pack2(h2, h3));
    WL[j] = make_uint2(pack2(l0, l1), pack2(l2, l3));
}

// ---------------------------------------------------------------------------
__global__ void init_kernel(const float* __restrict__ E,
                            const float* __restrict__ eh,
                            const float* __restrict__ ec) {
    int i = blockIdx.x * blockDim.x + threadIdx.x;   // 0 .. B*H
    int k = i & (H - 1);
    __half hi, lo;
    split_f16(E[SOS_INDEX * H + k], hi, lo);         // scalar 4B read
    g_xH[i] = hi; g_xL[i] = lo;                      // scalar 2B writes
    split_f16(eh[i], hi, lo);
    g_hH[i] = hi; g_hL[i] = lo;
    g_c[i] = ec[i];                                  // scalar 4B
}

// ---------------------------------------------------------------------------
// Pure-fp16 tensor-core GEMM on pre-split operands.
//   C = Ah*Bh + (Al*Bh + Ah*Bl) / 2048
// Global loads: uint4-unit indexing. SMEM tiles: uint4[rows][9] (=72 halves,
// 144B rows), whole-uint4 stores; consumer reads are 4B at even half indices.
// ---------------------------------------------------------------------------
#define BKH 64      // halves of K per tile
#define ROWU 9      // uint4 per SMEM row (8 data + 1 skew)
#define ROWH (ROWU*8)

template<int KTOT, int BN, bool CONCAT>
__global__ __launch_bounds__(256)
void mma_gemm(const uint4* __restrict__ BaH, const uint4* __restrict__ BaL,
              const uint4* __restrict__ BbH, const uint4* __restrict__ BbL,
              const float* __restrict__ bias1, const float* __restrict__ bias2,
              float* __restrict__ out, int ldc) {
    constexpr int NF = BN / 16;           // n8 fragments per warp
    constexpr int BR = BN / 32;           // B loader row chunks
    __shared__ uint4 AsH4[64][ROWU];
    __shared__ uint4 AsL4[64][ROWU];
    __shared__ uint4 BsH4[BN][ROWU];
    __shared__ uint4 BsL4[BN][ROWU];
    const __half* AsH = (const __half*)AsH4;
    const __half* AsL = (const __half*)AsL4;
    const __half* BsH = (const __half*)BsH4;
    const __half* BsL = (const __half*)BsL4;

    const int n0blk = blockIdx.x * BN;
    const int tid   = threadIdx.x;
    const int warp  = tid >> 5;
    const int lane  = tid & 31;
    const int gid   = lane >> 2;
    const int tig   = lane & 3;

    const int m0  = (warp >> 1) * 16;      // warp M offset (0,16,32,48)
    const int n0w = (warp & 1) * (BN / 2); // warp N offset

    const int lm  = tid >> 3;              // loader row 0..31
    const int lv  = tid & 7;               // loader uint4 column 0..7 (=8 halves)

    uint4 aH[2], aL[2];
    uint4 bH[BR], bL[BR];

    auto gload = [&](int k0) {
        const int kv = (k0 >> 3) + lv;     // uint4 column in K
        #pragma unroll
        for (int r = 0; r < 2; r++) {
            int m = lm + r * 32;
            if (CONCAT) {
                if (kv < H / 8) {
                    aH[r] = g_xH_raw[m * (H / 8) + kv];
                    aL[r] = g_xL_raw[m * (H / 8) + kv];
                } else {
                    aH[r] = g_hH_raw[m * (H / 8) + kv - H / 8];
                    aL[r] = g_hL_raw[m * (H / 8) + kv - H / 8];
                }
            } else {
                aH[r] = g_hH_raw[m * (H / 8) + kv];
                aL[r] = g_hL_raw[m * (H / 8) + kv];
            }
        }
        #pragma unroll
        for (int r = 0; r < BR; r++) {
            size_t n = (size_t)n0blk + lm + r * 32;
            if (CONCAT) {
                if (kv < H / 8) {
                    bH[r] = BaH[n * (H / 8) + kv];
                    bL[r] = BaL[n * (H / 8) + kv];
                } else {
                    bH[r] = BbH[n * (H / 8) + kv - H / 8];
                    bL[r] = BbL[n * (H / 8) + kv - H / 8];
                }
            } else {
                bH[r] = BaH[n * (KTOT / 8) + kv];
                bL[r] = BaL[n * (KTOT / 8) + kv];
            }
        }
    };

    const int sv = lv;                     // SMEM uint4 column for this loader
    auto store_tiles = [&]() {
        #pragma unroll
        for (int r = 0; r < 2; r++) {
            int m = lm + r * 32;
            AsH4[m][sv] = aH[r];
            AsL4[m][sv] = aL[r];
        }
        #pragma unroll
        for (int r = 0; r < BR; r++) {
            int n = lm + r * 32;
            BsH4[n][sv] = bH[r];
            BsL4[n][sv] = bL[r];
        }
    };

    float c1[NF][4], c2[NF][4];
    #pragma unroll
    for (int nf = 0; nf < NF; nf++)
        #pragma unroll
        for (int j = 0; j < 4; j++) { c1[nf][j] = 0.f; c2[nf][j] = 0.f; }

    gload(0);
    for (int k0 = 0; k0 < KTOT; k0 += BKH) {
        store_tiles();
        __syncthreads();
        if (k0 + BKH < KTOT) gload(k0 + BKH);   // prefetch next tile into regs

        #pragma unroll
        for (int ks = 0; ks < BKH / 16; ks++) {
            const int kb = ks * 16;
            const int ra = (m0 + gid) * ROWH, rb = (m0 + gid + 8) * ROWH;
            uint32_t ah[4], al[4];
            ah[0] = *reinterpret_cast<const uint32_t*>(AsH + ra + kb + 2 * tig);
            ah[1] = *reinterpret_cast<const uint32_t*>(AsH + rb + kb + 2 * tig);
            ah[2] = *reinterpret_cast<const uint32_t*>(AsH + ra + kb + 8 + 2 * tig);
            ah[3] = *reinterpret_cast<const uint32_t*>(AsH + rb + kb + 8 + 2 * tig);
            al[0] = *reinterpret_cast<const uint32_t*>(AsL + ra + kb + 2 * tig);
            al[1] = *reinterpret_cast<const uint32_t*>(AsL + rb + kb + 2 * tig);
            al[2] = *reinterpret_cast<const uint32_t*>(AsL + ra + kb + 8 + 2 * tig);
            al[3] = *reinterpret_cast<const uint32_t*>(AsL + rb + kb + 8 + 2 * tig);

            uint32_t bh[NF][2];
            #pragma unroll
            for (int nf = 0; nf < NF; nf++) {
                int n = (n0w + nf * 8 + gid) * ROWH;
                bh[nf][0] = *reinterpret_cast<const uint32_t*>(BsH + n + kb + 2 * tig);
                bh[nf][1] = *reinterpret_cast<const uint32_t*>(BsH + n + kb + 8 + 2 * tig);
            }
            #pragma unroll
            for (int nf = 0; nf < NF; nf++) mma_f16(c2[nf], al, bh[nf][0], bh[nf][1]);
            #pragma unroll
            for (int nf = 0; nf < NF; nf++) mma_f16(c1[nf], ah, bh[nf][0], bh[nf][1]);
            #pragma unroll
            for (int nf = 0; nf < NF; nf++) {
                int n = (n0w + nf * 8 + gid) * ROWH;
                uint32_t bl0 = *reinterpret_cast<const uint32_t*>(BsL + n + kb + 2 * tig);
                uint32_t bl1 = *reinterpret_cast<const uint32_t*>(BsL + n + kb + 8 + 2 * tig);
                mma_f16(c2[nf], ah, bl0, bl1);
            }
        }
        __syncthreads();
    }

    // ---- epilogue: combine chains + bias + SCALAR float stores ----
    const int mr0 = m0 + gid;
    const int mr1 = m0 + gid + 8;
    #pragma unroll
    for (int nf = 0; nf < NF; nf++) {
        int nn = n0blk + n0w + nf * 8 + tig * 2;
        float b0 = bias1[nn]     + (CONCAT ? bias2[nn]     : 0.f);
        float b1 = bias1[nn + 1] + (CONCAT ? bias2[nn + 1] : 0.f);
        out[(size_t)mr0 * ldc + nn]     = c1[nf][0] + c2[nf][0] * RINV + b0;
        out[(size_t)mr0 * ldc + nn + 1] = c1[nf][1] + c2[nf][1] * RINV + b1;
        out[(size_t)mr1 * ldc + nn]     = c1[nf][2] + c2[nf][2] * RINV + b0;
        out[(size_t)mr1 * ldc + nn + 1] = c1[nf][3] + c2[nf][3] * RINV + b1;
    }
}

// ---------------------------------------------------------------------------
// LSTM cell: writes c (f32) and SPLIT h (scalar halves).
// ---------------------------------------------------------------------------
__global__ void cell_kernel() {
    int i = blockIdx.x * blockDim.x + threadIdx.x;   // B*H
    int b = i >> 10;
    int j = i & (H - 1);
    const float* g = g_gates + b * GATES;
    float ig = g[j], fg = g[j + H], gg = g[j + 2 * H], og = g[j + 3 * H];
    float c  = g_c[i];
    float si = 1.f / (1.f + expf(-ig));
    float sf = 1.f / (1.f + expf(-fg));
    float so = 1.f / (1.f + expf(-og));
    float cn = sf * c + si * tanhf(gg);
    float hn = so * tanhf(cn);
    g_c[i] = cn;
    __half hi, lo;
    split_f16(hn, hi, lo);
    g_hH[i] = hi; g_hL[i] = lo;
}

// ---------------------------------------------------------------------------
// Per-batch-row: argmax (first-index tiebreak), softmax EOS prob,
// greedy feedback gather x_next = E[argmax] written pre-split (scalar).
// ---------------------------------------------------------------------------
__global__ __launch_bounds__(1024)
void softmax_argmax(const float* __restrict__ logits, const float* __restrict__ E,
                    float* __restrict__ mask_out) {
    const int b    = blockIdx.x;
    const int tid  = threadIdx.x;
    const int lane = tid & 31;
    const int wrp  = tid >> 5;
    const float4* row4 = reinterpret_cast<const float4*>(logits + (size_t)b * V);

    float best = -INFINITY; int besti = 0x7fffffff;
    for (int q = tid; q < V / 4; q += 1024) {
        float4 x = row4[q];
        int v = q * 4;
        if (x.x > best) { best = x.x; besti = v; }
        if (x.y > best) { best = x.y; besti = v + 1; }
        if (x.z > best) { best = x.z; besti = v + 2; }
        if (x.w > best) { best = x.w; besti = v + 3; }
    }
    #pragma unroll
    for (int s = 16; s > 0; s >>= 1) {
        float ov = __shfl_down_sync(0xffffffffu, best, s);
        int   oi = __shfl_down_sync(0xffffffffu, besti, s);
        if (ov > best || (ov == best && oi < besti)) { best = ov; besti = oi; }
    }
    __shared__ float swv[32];
    __shared__ int   swi[32];
    if (lane == 0) { swv[wrp] = best; swi[wrp] = besti; }
    __syncthreads();
    __shared__ float s_gmax;
    __shared__ int   s_amax;
    if (wrp == 0) {
        float bv = swv[lane]; int bi = swi[lane];
        #pragma unroll
        for (int s = 16; s > 0; s >>= 1) {
            float ov = __shfl_down_sync(0xffffffffu, bv, s);
            int   oi = __shfl_down_sync(0xffffffffu, bi, s);
            if (ov > bv || (ov == bv && oi < bi)) { bv = ov; bi = oi; }
        }
        if (lane == 0) { s_gmax = bv; s_amax = bi; }
    }
    __syncthreads();
    const float gmax = s_gmax;
    const int   amax = s_amax;

    float sum = 0.f;
    for (int q = tid; q < V / 4; q += 1024) {
        float4 x = row4[q];
        sum += expf(x.x - gmax) + expf(x.y - gmax)
             + expf(x.z - gmax) + expf(x.w - gmax);
    }
    #pragma unroll
    for (int s = 16; s > 0; s >>= 1)
        sum += __shfl_down_sync(0xffffffffu, sum, s);
    __shared__ float ssum[32];
    if (lane == 0) ssum[wrp] = sum;
    __syncthreads();
    if (wrp == 0) {
        float t = ssum[lane];
        #pragma unroll
        for (int s = 16; s > 0; s >>= 1)
            t += __shfl_down_sync(0xffffffffu, t, s);
        if (lane == 0)
            mask_out[b] = expf(logits[(size_t)b * V + EOS_INDEX] - gmax) / t;
    }

    // greedy feedback: x_next = E[argmax], stored pre-split (scalar 2B)
    __half hi, lo;
    split_f16(E[(size_t)amax * H + tid], hi, lo);
    g_xH[b * H + tid] = hi;
    g_xL[b * H + tid] = lo;
}

// ---------------------------------------------------------------------------
extern "C" void kernel_launch(void* const* d_in, const int* in_sizes, int n_in,
                              void* d_out, int out_size) {
    const float* E    = (const float*)d_in[0];
    const float* Wih  = (const float*)d_in[1];
    const float* Whh  = (const float*)d_in[2];
    const float* bih  = (const float*)d_in[3];
    const float* bhh  = (const float*)d_in[4];
    const float* Wout = (const float*)d_in[5];
    const float* bout = (const float*)d_in[6];
    const float* eh   = (const float*)d_in[7];
    const float* ec   = (const float*)d_in[8];

    float* out   = (float*)d_out;                       // [T][B][V] logits
    float* masks = out + (size_t)T * B * V;             // [T][B]

    // Resolve DEVICE addresses of all symbols passed as kernel args.
    void *pWihH, *pWihL, *pWhhH, *pWhhL, *pWoutH, *pWoutL, *pGates;
    cudaGetSymbolAddress(&pWihH, g_WihH_raw);
    cudaGetSymbolAddress(&pWihL, g_WihL_raw);
    cudaGetSymbolAddress(&pWhhH, g_WhhH_raw);
    cudaGetSymbolAddress(&pWhhL, g_WhhL_raw);
    cudaGetSymbolAddress(&pWoutH, g_WoutH_raw);
    cudaGetSymbolAddress(&pWoutL, g_WoutL_raw);
    cudaGetSymbolAddress(&pGates, g_gates_raw);

    // One-time (per launch) weight pre-split. grid = elems/4/256.
    split_weights<<<GATES * H / 1024, 256>>>(
        (const float4*)Wih, (uint2*)pWihH, (uint2*)pWihL);
    split_weights<<<GATES * H / 1024, 256>>>(
        (const float4*)Whh, (uint2*)pWhhH, (uint2*)pWhhL);
    split_weights<<<(int)((size_t)V * H / 1024), 256>>>(
        (const float4*)Wout, (uint2*)pWoutH, (uint2*)pWoutL);

    init_kernel<<<(B * H) / 256, 256>>>(E, eh, ec);
    for (int t = 0; t < T; t++) {
        float* lg = out + (size_t)t * B * V;
        // gates: [64 x 4096] = [x|h] * [Wih|Whh]^T, BN=32 -> 128 blocks
        mma_gemm<2 * H, 32, true><<<GATES / 32, 256>>>(
            (const uint4*)pWihH, (const uint4*)pWihL,
            (const uint4*)pWhhH, (const uint4*)pWhhL,
            bih, bhh, (float*)pGates, GATES);
        cell_kernel<<<(B * H) / 256, 256>>>();
        // logits: [64 x 32000] = h * Wout^T, BN=64 -> 500 blocks
        mma_gemm<H, 64, false><<<V / 64, 256>>>(
            (const uint4*)pWoutH, (const uint4*)pWoutL,
            nullptr, nullptr, bout, nullptr, lg, V);
        softmax_argmax<<<B, 1024>>>(lg, E, masks + t * B);
    }
}

// round 13
// speedup vs baseline: 2.7539x; 1.0443x over previous
#include <cuda_runtime.h>
#include <cuda_fp16.h>
#include <math.h>
#include <stdint.h>

#define V 32000
#define H 1024
#define T 32
#define B 64
#define SOS_INDEX 1
#define EOS_INDEX 2
#define GATES (4*H)

#define RSCALE 2048.0f
#define RINV   (1.0f / 2048.0f)

// ---------------------------------------------------------------------------
// Persistent state. EVERY global that receives accesses wider than 4 bytes
// is vector-typed and accessed by vector-unit indexing.
// ---------------------------------------------------------------------------
__device__ float4 g_c_raw[B*H/4];
__device__ float4 g_gates_raw[B*GATES/4];
__device__ uint4  g_xH_raw[B*H/8];
__device__ uint4  g_xL_raw[B*H/8];
__device__ uint4  g_hH_raw[B*H/8];
__device__ uint4  g_hL_raw[B*H/8];
__device__ uint4  g_WihH_raw[GATES*H/8];
__device__ uint4  g_WihL_raw[GATES*H/8];
__device__ uint4  g_WhhH_raw[GATES*H/8];
__device__ uint4  g_WhhL_raw[GATES*H/8];
__device__ uint4  g_WoutH_raw[(size_t)V*H/8];
__device__ uint4  g_WoutL_raw[(size_t)V*H/8];

#define g_c     ((float*)g_c_raw)
#define g_gates ((float*)g_gates_raw)
#define g_xH    ((__half*)g_xH_raw)
#define g_xL    ((__half*)g_xL_raw)
#define g_hH    ((__half*)g_hH_raw)
#define g_hL    ((__half*)g_hL_raw)

// ---------------------------------------------------------------------------
__device__ __forceinline__ void split_f16(float x, __half& hi, __half& lo) {
    hi = __float2half_rn(x);
    lo = __float2half_rn((x - __half2float(hi)) * RSCALE);
}
__device__ __forceinline__ uint32_t pack2(__half a, __half b) {
    __half2 h = __halves2half2(a, b);
    return *reinterpret_cast<uint32_t*>(&h);
}
__device__ __forceinline__ void mma_f16(float c[4], const uint32_t a[4],
                                        uint32_t b0, uint32_t b1) {
    asm volatile(
        "mma.sync.aligned.m16n8k16.row.col.f32.f16.f16.f32 "
        "{%0,%1,%2,%3}, {%4,%5,%6,%7}, {%8,%9}, {%0,%1,%2,%3};"
        : "+f"(c[0]), "+f"(c[1]), "+f"(c[2]), "+f"(c[3])
        : "r"(a[0]), "r"(a[1]), "r"(a[2]), "r"(a[3]), "r"(b0), "r"(b1));
}
__device__ __forceinline__ void cp16(uint32_t dst_smem, const uint4* src) {
    asm volatile("cp.async.cg.shared.global [%0], [%1], 16;"
                 :: "r"(dst_smem), "l"(src));
}

// ---------------------------------------------------------------------------
// Weight pre-split: one float4 -> one uint2 of hi halves + one of lo halves.
// ---------------------------------------------------------------------------
__global__ __launch_bounds__(256)
void split_weights(const float4* __restrict__ W, uint2* __restrict__ WH,
                   uint2* __restrict__ WL) {
    size_t j = (size_t)blockIdx.x * 256 + threadIdx.x;   // float4 index
    float4 v = W[j];
    __half h0, l0, h1, l1, h2, l2, h3, l3;
    split_f16(v.x, h0, l0); split_f16(v.y, h1, l1);
    split_f16(v.z, h2, l2); split_f16(v.w, h3, l3);
    WH[j] = make_uint2(pack2(h0, h1), pack2(h2, h3));
    WL[j] = make_uint2(pack2(l0, l1), pack2(l2, l3));
}

// ---------------------------------------------------------------------------
__global__ void init_kernel(const float* __restrict__ E,
                            const float* __restrict__ eh,
                            const float* __restrict__ ec) {
    int i = blockIdx.x * blockDim.x + threadIdx.x;   // 0 .. B*H
    int k = i & (H - 1);
    __half hi, lo;
    split_f16(E[SOS_INDEX * H + k], hi, lo);
    g_xH[i] = hi; g_xL[i] = lo;
    split_f16(eh[i], hi, lo);
    g_hH[i] = hi; g_hL[i] = lo;
    g_c[i] = ec[i];
}

// ---------------------------------------------------------------------------
// Pure-fp16 tensor-core GEMM on pre-split operands.
//   C = Ah*Bh + (Al*Bh + Ah*Bl) / 2048
// 2-stage cp.async (LDGSTS) pipeline into dynamic SMEM. Per stage layout
// (uint4 units): AsH[64][9] | AsL[64][9] | BsH[BN][9] | BsL[BN][9].
// ---------------------------------------------------------------------------
#define BKH 64      // halves of K per tile
#define ROWU 9      // uint4 per SMEM row (8 data + 1 skew)
#define ROWH (ROWU*8)

template<int KTOT, int BN, bool CONCAT>
__global__ __launch_bounds__(256)
void mma_gemm(const uint4* __restrict__ BaH, const uint4* __restrict__ BaL,
              const uint4* __restrict__ BbH, const uint4* __restrict__ BbL,
              const float* __restrict__ bias1, const float* __restrict__ bias2,
              float* __restrict__ out, int ldc) {
    constexpr int NF  = BN / 16;              // n8 fragments per warp
    constexpr int BR  = BN / 32;              // B loader row chunks
    constexpr int STG = (128 + 2 * BN) * ROWU;// uint4 per stage
    constexpr int NT  = KTOT / BKH;           // number of k tiles
    extern __shared__ uint4 smem[];

    const int n0blk = blockIdx.x * BN;
    const int tid   = threadIdx.x;
    const int warp  = tid >> 5;
    const int lane  = tid & 31;
    const int gid   = lane >> 2;
    const int tig   = lane & 3;

    const int m0  = (warp >> 1) * 16;      // warp M offset (0,16,32,48)
    const int n0w = (warp & 1) * (BN / 2); // warp N offset

    const int lm  = tid >> 3;              // loader row 0..31
    const int lv  = tid & 7;               // loader uint4 column 0..7

    auto issue_tile = [&](int k0, int stage) {
        uint4* sb = smem + (size_t)stage * STG;
        const int kv = (k0 >> 3) + lv;     // uint4 column in K
        #pragma unroll
        for (int r = 0; r < 2; r++) {
            int m = lm + r * 32;
            uint32_t dH = (uint32_t)__cvta_generic_to_shared(sb + m * ROWU + lv);
            uint32_t dL = (uint32_t)__cvta_generic_to_shared(sb + (64 + m) * ROWU + lv);
            const uint4 *sH, *sL;
            if (CONCAT) {
                if (kv < H / 8) {
                    sH = g_xH_raw + m * (H / 8) + kv;
                    sL = g_xL_raw + m * (H / 8) + kv;
                } else {
                    sH = g_hH_raw + m * (H / 8) + kv - H / 8;
                    sL = g_hL_raw + m * (H / 8) + kv - H / 8;
                }
            } else {
                sH = g_hH_raw + m * (H / 8) + kv;
                sL = g_hL_raw + m * (H / 8) + kv;
            }
            cp16(dH, sH);
            cp16(dL, sL);
        }
        #pragma unroll
        for (int r = 0; r < BR; r++) {
            int nloc = lm + r * 32;
            size_t n = (size_t)n0blk + nloc;
            uint32_t dH = (uint32_t)__cvta_generic_to_shared(sb + (128 + nloc) * ROWU + lv);
            uint32_t dL = (uint32_t)__cvta_generic_to_shared(sb + (128 + BN + nloc) * ROWU + lv);
            const uint4 *sH, *sL;
            if (CONCAT) {
                if (kv < H / 8) {
                    sH = BaH + n * (H / 8) + kv;
                    sL = BaL + n * (H / 8) + kv;
                } else {
                    sH = BbH + n * (H / 8) + kv - H / 8;
                    sL = BbL + n * (H / 8) + kv - H / 8;
                }
            } else {
                sH = BaH + n * (KTOT / 8) + kv;
                sL = BaL + n * (KTOT / 8) + kv;
            }
            cp16(dH, sH);
            cp16(dL, sL);
        }
        asm volatile("cp.async.commit_group;" ::: "memory");
    };

    float c1[NF][4], c2[NF][4];
    #pragma unroll
    for (int nf = 0; nf < NF; nf++)
        #pragma unroll
        for (int j = 0; j < 4; j++) { c1[nf][j] = 0.f; c2[nf][j] = 0.f; }

    issue_tile(0, 0);

    #pragma unroll 1
    for (int kt = 0; kt < NT; kt++) {
        if (kt + 1 < NT) {
            issue_tile((kt + 1) * BKH, (kt + 1) & 1);
            asm volatile("cp.async.wait_group 1;" ::: "memory");
        } else {
            asm volatile("cp.async.wait_group 0;" ::: "memory");
        }
        __syncthreads();

        const __half* base = (const __half*)(smem + (size_t)(kt & 1) * STG);
        const __half* AsH = base;
        const __half* AsL = base + 64 * ROWH;
        const __half* BsH = base + 128 * ROWH;
        const __half* BsL = base + (128 + BN) * ROWH;

        #pragma unroll
        for (int ks = 0; ks < BKH / 16; ks++) {
            const int kb = ks * 16;
            const int ra = (m0 + gid) * ROWH, rb = (m0 + gid + 8) * ROWH;
            uint32_t ah[4], al[4];
            ah[0] = *reinterpret_cast<const uint32_t*>(AsH + ra + kb + 2 * tig);
            ah[1] = *reinterpret_cast<const uint32_t*>(AsH + rb + kb + 2 * tig);
            ah[2] = *reinterpret_cast<const uint32_t*>(AsH + ra + kb + 8 + 2 * tig);
            ah[3] = *reinterpret_cast<const uint32_t*>(AsH + rb + kb + 8 + 2 * tig);
            al[0] = *reinterpret_cast<const uint32_t*>(AsL + ra + kb + 2 * tig);
            al[1] = *reinterpret_cast<const uint32_t*>(AsL + rb + kb + 2 * tig);
            al[2] = *reinterpret_cast<const uint32_t*>(AsL + ra + kb + 8 + 2 * tig);
            al[3] = *reinterpret_cast<const uint32_t*>(AsL + rb + kb + 8 + 2 * tig);

            uint32_t bh[NF][2];
            #pragma unroll
            for (int nf = 0; nf < NF; nf++) {
                int n = (n0w + nf * 8 + gid) * ROWH;
                bh[nf][0] = *reinterpret_cast<const uint32_t*>(BsH + n + kb + 2 * tig);
                bh[nf][1] = *reinterpret_cast<const uint32_t*>(BsH + n + kb + 8 + 2 * tig);
            }
            #pragma unroll
            for (int nf = 0; nf < NF; nf++) mma_f16(c2[nf], al, bh[nf][0], bh[nf][1]);
            #pragma unroll
            for (int nf = 0; nf < NF; nf++) mma_f16(c1[nf], ah, bh[nf][0], bh[nf][1]);
            #pragma unroll
            for (int nf = 0; nf < NF; nf++) {
                int n = (n0w + nf * 8 + gid) * ROWH;
                uint32_t bl0 = *reinterpret_cast<const uint32_t*>(BsL + n + kb + 2 * tig);
                uint32_t bl1 = *reinterpret_cast<const uint32_t*>(BsL + n + kb + 8 + 2 * tig);
                mma_f16(c2[nf], ah, bl0, bl1);
            }
        }
        __syncthreads();
    }

    // ---- epilogue: combine chains + bias + SCALAR float stores ----
    const int mr0 = m0 + gid;
    const int mr1 = m0 + gid + 8;
    #pragma unroll
    for (int nf = 0; nf < NF; nf++) {
        int nn = n0blk + n0w + nf * 8 + tig * 2;
        float b0 = bias1[nn]     + (CONCAT ? bias2[nn]     : 0.f);
        float b1 = bias1[nn + 1] + (CONCAT ? bias2[nn + 1] : 0.f);
        out[(size_t)mr0 * ldc + nn]     = c1[nf][0] + c2[nf][0] * RINV + b0;
        out[(size_t)mr0 * ldc + nn + 1] = c1[nf][1] + c2[nf][1] * RINV + b1;
        out[(size_t)mr1 * ldc + nn]     = c1[nf][2] + c2[nf][2] * RINV + b0;
        out[(size_t)mr1 * ldc + nn + 1] = c1[nf][3] + c2[nf][3] * RINV + b1;
    }
}

// ---------------------------------------------------------------------------
// LSTM cell: writes c (f32) and SPLIT h (scalar halves).
// ---------------------------------------------------------------------------
__global__ void cell_kernel() {
    int i = blockIdx.x * blockDim.x + threadIdx.x;   // B*H
    int b = i >> 10;
    int j = i & (H - 1);
    const float* g = g_gates + b * GATES;
    float ig = g[j], fg = g[j + H], gg = g[j + 2 * H], og = g[j + 3 * H];
    float c  = g_c[i];
    float si = 1.f / (1.f + expf(-ig));
    float sf = 1.f / (1.f + expf(-fg));
    float so = 1.f / (1.f + expf(-og));
    float cn = sf * c + si * tanhf(gg);
    float hn = so * tanhf(cn);
    g_c[i] = cn;
    __half hi, lo;
    split_f16(hn, hi, lo);
    g_hH[i] = hi; g_hL[i] = lo;
}

// ---------------------------------------------------------------------------
// Per-batch-row: argmax (first-index tiebreak), softmax EOS prob,
// greedy feedback gather x_next = E[argmax] written pre-split (scalar).
// ---------------------------------------------------------------------------
__global__ __launch_bounds__(1024)
void softmax_argmax(const float* __restrict__ logits, const float* __restrict__ E,
                    float* __restrict__ mask_out) {
    const int b    = blockIdx.x;
    const int tid  = threadIdx.x;
    const int lane = tid & 31;
    const int wrp  = tid >> 5;
    const float4* row4 = reinterpret_cast<const float4*>(logits + (size_t)b * V);

    float best = -INFINITY; int besti = 0x7fffffff;
    for (int q = tid; q < V / 4; q += 1024) {
        float4 x = row4[q];
        int v = q * 4;
        if (x.x > best) { best = x.x; besti = v; }
        if (x.y > best) { best = x.y; besti = v + 1; }
        if (x.z > best) { best = x.z; besti = v + 2; }
        if (x.w > best) { best = x.w; besti = v + 3; }
    }
    #pragma unroll
    for (int s = 16; s > 0; s >>= 1) {
        float ov = __shfl_down_sync(0xffffffffu, best, s);
        int   oi = __shfl_down_sync(0xffffffffu, besti, s);
        if (ov > best || (ov == best && oi < besti)) { best = ov; besti = oi; }
    }
    __shared__ float swv[32];
    __shared__ int   swi[32];
    if (lane == 0) { swv[wrp] = best; swi[wrp] = besti; }
    __syncthreads();
    __shared__ float s_gmax;
    __shared__ int   s_amax;
    if (wrp == 0) {
        float bv = swv[lane]; int bi = swi[lane];
        #pragma unroll
        for (int s = 16; s > 0; s >>= 1) {
            float ov = __shfl_down_sync(0xffffffffu, bv, s);
            int   oi = __shfl_down_sync(0xffffffffu, bi, s);
            if (ov > bv || (ov == bv && oi < bi)) { bv = ov; bi = oi; }
        }
        if (lane == 0) { s_gmax = bv; s_amax = bi; }
    }
    __syncthreads();
    const float gmax = s_gmax;
    const int   amax = s_amax;

    float sum = 0.f;
    for (int q = tid; q < V / 4; q += 1024) {
        float4 x = row4[q];
        sum += expf(x.x - gmax) + expf(x.y - gmax)
             + expf(x.z - gmax) + expf(x.w - gmax);
    }
    #pragma unroll
    for (int s = 16; s > 0; s >>= 1)
        sum += __shfl_down_sync(0xffffffffu, sum, s);
    __shared__ float ssum[32];
    if (lane == 0) ssum[wrp] = sum;
    __syncthreads();
    if (wrp == 0) {
        float t = ssum[lane];
        #pragma unroll
        for (int s = 16; s > 0; s >>= 1)
            t += __shfl_down_sync(0xffffffffu, t, s);
        if (lane == 0)
            mask_out[b] = expf(logits[(size_t)b * V + EOS_INDEX] - gmax) / t;
    }

    // greedy feedback: x_next = E[argmax], stored pre-split (scalar 2B)
    __half hi, lo;
    split_f16(E[(size_t)amax * H + tid], hi, lo);
    g_xH[b * H + tid] = hi;
    g_xL[b * H + tid] = lo;
}

// ---------------------------------------------------------------------------
extern "C" void kernel_launch(void* const* d_in, const int* in_sizes, int n_in,
                              void* d_out, int out_size) {
    const float* E    = (const float*)d_in[0];
    const float* Wih  = (const float*)d_in[1];
    const float* Whh  = (const float*)d_in[2];
    const float* bih  = (const float*)d_in[3];
    const float* bhh  = (const float*)d_in[4];
    const float* Wout = (const float*)d_in[5];
    const float* bout = (const float*)d_in[6];
    const float* eh   = (const float*)d_in[7];
    const float* ec   = (const float*)d_in[8];

    float* out   = (float*)d_out;                       // [T][B][V] logits
    float* masks = out + (size_t)T * B * V;             // [T][B]

    // Resolve DEVICE addresses of all symbols passed as kernel args.
    void *pWihH, *pWihL, *pWhhH, *pWhhL, *pWoutH, *pWoutL, *pGates;
    cudaGetSymbolAddress(&pWihH, g_WihH_raw);
    cudaGetSymbolAddress(&pWihL, g_WihL_raw);
    cudaGetSymbolAddress(&pWhhH, g_WhhH_raw);
    cudaGetSymbolAddress(&pWhhL, g_WhhL_raw);
    cudaGetSymbolAddress(&pWoutH, g_WoutH_raw);
    cudaGetSymbolAddress(&pWoutL, g_WoutL_raw);
    cudaGetSymbolAddress(&pGates, g_gates_raw);

    // Dynamic SMEM sizes (2 stages). Gates: (128+64)*9*16*2 = 55296 B.
    // Logits: (128+128)*9*16*2 = 73728 B. Both exceed the 48KB default.
    const int smem_gates  = (128 + 2 * 32) * ROWU * 16 * 2;
    const int smem_logits = (128 + 2 * 64) * ROWU * 16 * 2;
    cudaFuncSetAttribute(mma_gemm<2 * H, 32, true>,
                         cudaFuncAttributeMaxDynamicSharedMemorySize, smem_gates);
    cudaFuncSetAttribute(mma_gemm<H, 64, false>,
                         cudaFuncAttributeMaxDynamicSharedMemorySize, smem_logits);

    // One-time (per launch) weight pre-split. grid = elems/4/256.
    split_weights<<<GATES * H / 1024, 256>>>(
        (const float4*)Wih, (uint2*)pWihH, (uint2*)pWihL);
    split_weights<<<GATES * H / 1024, 256>>>(
        (const float4*)Whh, (uint2*)pWhhH, (uint2*)pWhhL);
    split_weights<<<(int)((size_t)V * H / 1024), 256>>>(
        (const float4*)Wout, (uint2*)pWoutH, (uint2*)pWoutL);

    init_kernel<<<(B * H) / 256, 256>>>(E, eh, ec);
    for (int t = 0; t < T; t++) {
        float* lg = out + (size_t)t * B * V;
        // gates: [64 x 4096] = [x|h] * [Wih|Whh]^T, BN=32 -> 128 blocks
        mma_gemm<2 * H, 32, true><<<GATES / 32, 256, smem_gates>>>(
            (const uint4*)pWihH, (const uint4*)pWihL,
            (const uint4*)pWhhH, (const uint4*)pWhhL,
            bih, bhh, (float*)pGates, GATES);
        cell_kernel<<<(B * H) / 256, 256>>>();
        // logits: [64 x 32000] = h * Wout^T, BN=64 -> 500 blocks
        mma_gemm<H, 64, false><<<V / 64, 256, smem_logits>>>(
            (const uint4*)pWoutH, (const uint4*)pWoutL,
            nullptr, nullptr, bout, nullptr, lg, V);
        softmax_argmax<<<B, 1024>>>(lg, E, masks + t * B);
    }
}